// round 4
// baseline (speedup 1.0000x reference)
#include <cuda_runtime.h>

#define N 4096
#define NN (N * N)
#define NITERS 300
#define NBLK 128
#define TPB 1024
#define QS 0.015625f      // 2^-6 : dequant scale (exponent = g + c - QS*q)

// Quantized cost: q_ij = round(k * C_ij * 64), u16. 32MB, L2-resident.
__device__ unsigned short d_Q[NN];
__device__ float  d_F[N];
__device__ float  d_G[N];
__device__ double d_csum;
__device__ double d_emd;
__device__ float  d_k;          // log2(e)/eps
__device__ unsigned int g_bar;
__device__ unsigned int g_epoch;

__device__ __forceinline__ float ex2f(float x) {
    float y;
    asm("ex2.approx.ftz.f32 %0, %1;" : "=f"(y) : "f"(x));
    return y;
}
__device__ __forceinline__ float ldcg(const float* p) { return __ldcg(p); }

// ---------------------------------------------------------------- init
__global__ void k_init() {
    d_csum  = 0.0;
    d_emd   = 0.0;
    g_bar   = 0u;
    g_epoch = 0u;
}

// ---------------------------------------------------------------- distance helper
__device__ __forceinline__ float distf(float x0, float x1, float x2, float xx,
                                       float y0, float y1, float y2) {
    float yy  = y0 * y0 + y1 * y1 + y2 * y2;
    float dot = x0 * y0 + x1 * y1 + x2 * y2;
    float d2  = xx + yy - 2.0f * dot;
    return sqrtf(fmaxf(d2, 0.0f) + 1e-12f);
}

// ---------------------------------------------------------------- pass 1: csum only (no store); zero F/G
__global__ void k_sum(const float* __restrict__ x, const float* __restrict__ y) {
    __shared__ float sred[8];
    int i = blockIdx.x;
    float x0 = x[3 * i], x1 = x[3 * i + 1], x2 = x[3 * i + 2];
    float xx = x0 * x0 + x1 * x1 + x2 * x2;
    float acc = 0.0f;
    for (int j = threadIdx.x; j < N; j += 256)
        acc += distf(x0, x1, x2, xx, y[3 * j], y[3 * j + 1], y[3 * j + 2]);
    for (int o = 16; o; o >>= 1) acc += __shfl_down_sync(0xffffffffu, acc, o);
    if ((threadIdx.x & 31) == 0) sred[threadIdx.x >> 5] = acc;
    __syncthreads();
    if (threadIdx.x < 8) {
        acc = sred[threadIdx.x];
        for (int o = 4; o; o >>= 1) acc += __shfl_down_sync(0xffu, acc, o);
        if (threadIdx.x == 0) atomicAdd(&d_csum, (double)acc);
    }
    if (threadIdx.x == 0) { d_F[i] = 0.0f; d_G[i] = 0.0f; }
}

// ---------------------------------------------------------------- eps -> k
__global__ void k_eps() {
    double mean = d_csum / (double)NN;
    d_k = (float)(1.4426950408889634 / (0.02 * mean));
}

// ---------------------------------------------------------------- pass 2: quantize q = round(k*C*64)
__global__ void k_quant(const float* __restrict__ x, const float* __restrict__ y) {
    int i = blockIdx.x;
    float kq = d_k * 64.0f;
    float x0 = x[3 * i], x1 = x[3 * i + 1], x2 = x[3 * i + 2];
    float xx = x0 * x0 + x1 * x1 + x2 * x2;
    for (int j = threadIdx.x; j < N; j += 256) {
        float c = distf(x0, x1, x2, xx, y[3 * j], y[3 * j + 1], y[3 * j + 2]);
        d_Q[(size_t)i * N + j] = (unsigned short)__float2uint_rn(c * kq);
    }
}

// ---------------------------------------------------------------- grid barrier (no membar/IVALL)
__device__ __forceinline__ void gsync(unsigned int& ep) {
    __syncthreads();
    if (threadIdx.x == 0) {
        unsigned int t;
        asm volatile("atom.add.release.gpu.u32 %0, [%1], 1;"
                     : "=r"(t) : "l"(&g_bar) : "memory");
        if (t == NBLK - 1) {
            g_bar = 0u;
            asm volatile("st.release.gpu.u32 [%0], %1;"
                         :: "l"(&g_epoch), "r"(ep + 1u) : "memory");
        } else {
            unsigned int v;
            do {
                asm volatile("ld.acquire.gpu.u32 %0, [%1];"
                             : "=r"(v) : "l"(&g_epoch) : "memory");
            } while (v == ep);
        }
    }
    ep++;
    __syncthreads();
}

// ---------------------------------------------------------------- persistent Sinkhorn + final P*C
__global__ void __launch_bounds__(TPB, 1) k_persist(float* __restrict__ out) {
    __shared__ float sV[N];
    __shared__ float sr[32][33];
    const int tid = threadIdx.x;
    const int bid = blockIdx.x;
    const int wid = tid >> 5;
    const int ln  = tid & 31;
    unsigned int ep = 0u;

    for (int it = 0; it < NITERS; it++) {
        // ---- f pass: warp-per-row.  F_i <- F_i - log2(sum_j 2^(G_j - QS*q_ij + F_i - 12))
        for (int j = tid; j < N; j += TPB) sV[j] = ldcg(&d_G[j]);
        __syncthreads();
        {
            const int i = bid * 32 + wid;
            const float Fi = ldcg(&d_F[i]);
            const float c  = Fi - 12.0f;
            const uint4*  Br = (const uint4*)(d_Q + (size_t)i * N);   // 8 u16 per load
            const float4* V4 = (const float4*)sV;
            float s0 = 0.f, s1 = 0.f, s2 = 0.f, s3 = 0.f;
#pragma unroll 4
            for (int t = ln; t < N / 8; t += 32) {
                uint4  p  = Br[t];
                float4 ga = V4[2 * t];
                float4 gb = V4[2 * t + 1];
                s0 += ex2f(fmaf((float)(p.x & 0xFFFFu), -QS, ga.x + c));
                s1 += ex2f(fmaf((float)(p.x >> 16),     -QS, ga.y + c));
                s2 += ex2f(fmaf((float)(p.y & 0xFFFFu), -QS, ga.z + c));
                s3 += ex2f(fmaf((float)(p.y >> 16),     -QS, ga.w + c));
                s0 += ex2f(fmaf((float)(p.z & 0xFFFFu), -QS, gb.x + c));
                s1 += ex2f(fmaf((float)(p.z >> 16),     -QS, gb.y + c));
                s2 += ex2f(fmaf((float)(p.w & 0xFFFFu), -QS, gb.z + c));
                s3 += ex2f(fmaf((float)(p.w >> 16),     -QS, gb.w + c));
            }
            float s = (s0 + s1) + (s2 + s3);
            for (int o = 16; o; o >>= 1) s += __shfl_down_sync(0xffffffffu, s, o);
            if (ln == 0) d_F[i] = Fi - log2f(s);
        }
        gsync(ep);

        // ---- g pass: block-per-32-cols.  G_j <- G_j - log2(sum_i 2^(F_i - QS*q_ij + G_j - 12))
        for (int i = tid; i < N; i += TPB) sV[i] = ldcg(&d_F[i]);
        __syncthreads();
        {
            const int tx = ln, ty = wid;
            const int j  = bid * 32 + tx;
            const float Gj = ldcg(&d_G[j]);
            const float c  = Gj - 12.0f;
            const unsigned short* Qc = d_Q + j;
            float s0 = 0.f, s1 = 0.f, s2 = 0.f, s3 = 0.f;
#pragma unroll 4
            for (int i = ty; i < N; i += 128) {
                s0 += ex2f(fmaf((float)Qc[(size_t)i * N],        -QS, sV[i]      + c));
                s1 += ex2f(fmaf((float)Qc[(size_t)(i + 32) * N], -QS, sV[i + 32] + c));
                s2 += ex2f(fmaf((float)Qc[(size_t)(i + 64) * N], -QS, sV[i + 64] + c));
                s3 += ex2f(fmaf((float)Qc[(size_t)(i + 96) * N], -QS, sV[i + 96] + c));
            }
            sr[ty][tx] = (s0 + s1) + (s2 + s3);
            __syncthreads();
            float v = sr[tx][ty];
            for (int o = 16; o; o >>= 1) v += __shfl_down_sync(0xffffffffu, v, o);
            if (tx == 0) {
                int jj = bid * 32 + ty;
                d_G[jj] = ldcg(&d_G[jj]) - log2f(v);
            }
        }
        gsync(ep);
    }

    // ---- final: sum_ij P_ij * C_ij with C = QS*q/k; accumulate sum(term*q), scale at end
    for (int j = tid; j < N; j += TPB) sV[j] = ldcg(&d_G[j]);
    __syncthreads();
    {
        const int i = bid * 32 + wid;
        const float c = ldcg(&d_F[i]) - 24.0f;
        const uint4*  Br = (const uint4*)(d_Q + (size_t)i * N);
        const float4* V4 = (const float4*)sV;
        float a0 = 0.f, a1 = 0.f, a2 = 0.f, a3 = 0.f;
#pragma unroll 4
        for (int t = ln; t < N / 8; t += 32) {
            uint4  p  = Br[t];
            float4 ga = V4[2 * t];
            float4 gb = V4[2 * t + 1];
            float q0 = (float)(p.x & 0xFFFFu), q1 = (float)(p.x >> 16);
            float q2 = (float)(p.y & 0xFFFFu), q3 = (float)(p.y >> 16);
            float q4 = (float)(p.z & 0xFFFFu), q5 = (float)(p.z >> 16);
            float q6 = (float)(p.w & 0xFFFFu), q7 = (float)(p.w >> 16);
            a0 = fmaf(ex2f(fmaf(q0, -QS, ga.x + c)), q0, a0);
            a1 = fmaf(ex2f(fmaf(q1, -QS, ga.y + c)), q1, a1);
            a2 = fmaf(ex2f(fmaf(q2, -QS, ga.z + c)), q2, a2);
            a3 = fmaf(ex2f(fmaf(q3, -QS, ga.w + c)), q3, a3);
            a0 = fmaf(ex2f(fmaf(q4, -QS, gb.x + c)), q4, a0);
            a1 = fmaf(ex2f(fmaf(q5, -QS, gb.y + c)), q5, a1);
            a2 = fmaf(ex2f(fmaf(q6, -QS, gb.z + c)), q6, a2);
            a3 = fmaf(ex2f(fmaf(q7, -QS, gb.w + c)), q7, a3);
        }
        float s = (a0 + a1) + (a2 + a3);
        for (int o = 16; o; o >>= 1) s += __shfl_down_sync(0xffffffffu, s, o);
        if (ln == 0) sr[0][wid] = s;
    }
    __syncthreads();
    if (tid < 32) {
        float s = sr[0][tid];
        for (int o = 16; o; o >>= 1) s += __shfl_down_sync(0xffffffffu, s, o);
        if (tid == 0) atomicAdd(&d_emd, (double)s);
    }
    gsync(ep);
    if (bid == 0 && tid == 0) {
        double emd = __ldcg((const double*)&d_emd);
        out[0] = (float)(emd * (double)QS / (double)d_k);   // undo q scale: C = QS*q/k
    }
}

// ---------------------------------------------------------------- launch
extern "C" void kernel_launch(void* const* d_in, const int* in_sizes, int n_in,
                              void* d_out, int out_size) {
    const float* x = (const float*)d_in[0];
    const float* y = (const float*)d_in[1];
    float* out = (float*)d_out;

    k_init<<<1, 1>>>();
    k_sum<<<N, 256>>>(x, y);
    k_eps<<<1, 1>>>();
    k_quant<<<N, 256>>>(x, y);
    k_persist<<<NBLK, TPB>>>(out);
}